// round 1
// baseline (speedup 1.0000x reference)
#include <cuda_runtime.h>

#define N_FEAT   64
#define N_GATES  64
#define N_OUT    8
#define BASE_C   66      // N_FEAT + 2 (const0, const1)
#define MAX_CONN 130     // BASE_C + N_GATES
#define BT       128     // threads per block = samples per block

// top-2 logit indices per gate (depends only on gate_weights)
__device__ int2 g_top2[N_GATES];

// ---------------------------------------------------------------------------
// Prolog: argmax-2 over available logits per gate. Softmax is monotone, so
// top-2 of probs == top-2 of masked logits. Tie-break: earliest index wins
// the max slot; an equal later value lands in slot 2 (matches jax top_k).
// ---------------------------------------------------------------------------
__global__ void setup_topk_kernel(const float* __restrict__ gw) {
    int i = threadIdx.x;
    if (i >= N_GATES) return;
    int lim = BASE_C + i;                    // available columns for gate i
    float v1 = -3.0e38f, v2 = -3.0e38f;
    int i1 = 0, i2 = 0;
    for (int j = 0; j < lim; j++) {
        float v = gw[i * MAX_CONN + j];
        if (v > v1) { v2 = v1; i2 = i1; v1 = v; i1 = j; }
        else if (v > v2) { v2 = v; i2 = j; }
    }
    g_top2[i] = make_int2(i1, i2);
}

// ---------------------------------------------------------------------------
// Main kernel: one thread = one sample. Per-thread 130-slot buffer in shared,
// column-major [col*BT + tid] -> warp accesses one column at consecutive
// addresses (conflict-free). No __syncthreads needed after the initial one:
// each thread reads/writes only its own slots.
// ---------------------------------------------------------------------------
__global__ void __launch_bounds__(BT) circuit_kernel(
    const float* __restrict__ X,
    const float* __restrict__ W,       // [N_GATES, N_OUT]
    const float* __restrict__ scale,   // [N_OUT]
    float* __restrict__ out,           // [n, N_OUT]
    int n)
{
    extern __shared__ float smem[];
    float* buf  = smem;                              // MAX_CONN * BT floats
    float* sw   = smem + MAX_CONN * BT;              // 512 floats (W)
    int2*  sidx = (int2*)(sw + N_GATES * N_OUT);     // 64 int2

    const int tid = threadIdx.x;
    const long long row = (long long)blockIdx.x * BT + tid;

    // cooperative staging of W (512 floats) and top2 indices
    #pragma unroll
    for (int k = 0; k < (N_GATES * N_OUT) / BT; k++)
        sw[tid + k * BT] = W[tid + k * BT];
    if (tid < N_GATES) sidx[tid] = g_top2[tid];
    __syncthreads();

    if (row < n) {
        // Load my X row into my buffer column slots. Warp reads 32
        // consecutive rows -> contiguous 8KB region, fully consumed via L1.
        const float4* xv = (const float4*)(X + row * N_FEAT);
        #pragma unroll
        for (int c = 0; c < N_FEAT / 4; c++) {
            float4 v = xv[c];
            buf[(4 * c + 0) * BT + tid] = v.x;
            buf[(4 * c + 1) * BT + tid] = v.y;
            buf[(4 * c + 2) * BT + tid] = v.z;
            buf[(4 * c + 3) * BT + tid] = v.w;
        }
        buf[64 * BT + tid] = 0.0f;   // const 0 slot
        buf[65 * BT + tid] = 1.0f;   // const 1 slot
        // slots 66..129 are written before any read (gate i reads cols < 66+i)

        float acc[N_OUT];
        #pragma unroll
        for (int j = 0; j < N_OUT; j++) acc[j] = 0.0f;

        #pragma unroll 8
        for (int i = 0; i < N_GATES; i++) {
            int2 ab = sidx[i];                       // LDS.64, warp-broadcast
            float a = buf[ab.x * BT + tid];
            float b = buf[ab.y * BT + tid];
            float g = 1.0f - a * b;
            buf[(BASE_C + i) * BT + tid] = g;
            const float4* wr = (const float4*)(sw + i * N_OUT);
            float4 w0 = wr[0], w1 = wr[1];           // 2x LDS.128 broadcast
            acc[0] += g * w0.x; acc[1] += g * w0.y;
            acc[2] += g * w0.z; acc[3] += g * w0.w;
            acc[4] += g * w1.x; acc[5] += g * w1.y;
            acc[6] += g * w1.z; acc[7] += g * w1.w;
        }

        float4 o0, o1;
        o0.x = acc[0] * __ldg(&scale[0]);
        o0.y = acc[1] * __ldg(&scale[1]);
        o0.z = acc[2] * __ldg(&scale[2]);
        o0.w = acc[3] * __ldg(&scale[3]);
        o1.x = acc[4] * __ldg(&scale[4]);
        o1.y = acc[5] * __ldg(&scale[5]);
        o1.z = acc[6] * __ldg(&scale[6]);
        o1.w = acc[7] * __ldg(&scale[7]);
        float4* ov = (float4*)(out + row * N_OUT);
        ov[0] = o0;
        ov[1] = o1;
    }
}

// ---------------------------------------------------------------------------
// Launch
// ---------------------------------------------------------------------------
extern "C" void kernel_launch(void* const* d_in, const int* in_sizes, int n_in,
                              void* d_out, int out_size) {
    const float* X     = (const float*)d_in[0];
    const float* gw    = (const float*)d_in[1];
    const float* W     = (const float*)d_in[2];
    const float* scale = (const float*)d_in[3];
    float* out = (float*)d_out;

    const int n = in_sizes[0] / N_FEAT;

    setup_topk_kernel<<<1, N_GATES>>>(gw);

    const size_t smem_bytes =
        (size_t)MAX_CONN * BT * sizeof(float) +
        (size_t)N_GATES * N_OUT * sizeof(float) +
        (size_t)N_GATES * sizeof(int2);   // 69,120 B -> 3 blocks/SM

    cudaFuncSetAttribute(circuit_kernel,
                         cudaFuncAttributeMaxDynamicSharedMemorySize,
                         (int)smem_bytes);

    const int grid = (n + BT - 1) / BT;
    circuit_kernel<<<grid, BT, smem_bytes>>>(X, W, scale, out, n);
}